// round 16
// baseline (speedup 1.0000x reference)
#include <cuda_runtime.h>
#include <cuda_fp16.h>
#include <cstdint>
#include <cstddef>

// Xonv2D: out[b,o,h,w] = sum_{c,kh,kw} x[b,c,h+kh-1,w+kw-1] * W[h,w,o,c,kh,kw] + bias[h,w,o]
// B=4, CIN=COUT=16, K=3, H=W=128. Weights = 151MB streamed once -> HBM-bound.
// Round 16 = Round 15 with the FFMA2 pairing flipped to TAP-pairs: weight
// operand = the adjacent float2 in smem loaded directly as b64 (ld.shared.b64,
// zero broadcast MOVs). acc[cout][b] is f32x2 over (even,odd) taps; result =
// acc.x+acc.y. Kills all 72 dup-MOVs per iter; halves FFMA2 chain depth.

static constexpr int Hc = 128, Wc = 128;
static constexpr int GROUPS = 4096;                      // 4-pixel groups
static constexpr int FLOATS_PER_PX = 16 * 16 * 9;        // 2304
static constexpr int CHUNK_FLOATS  = 4 * FLOATS_PER_PX;  // 9216
static constexpr int CHUNK_BYTES   = CHUNK_FLOATS * 4;   // 36864
static constexpr int CSTR          = 19;                 // uint2 per c (18 + 1 pad)
static constexpr int XTILE_ELEMS   = 1152;
static constexpr int XTILE_BYTES   = 16 * CSTR * 8;      // 2432
static constexpr int SMEM_X_OFF    = 2 * CHUNK_BYTES;            // 73728
static constexpr int SMEM_OUT_OFF  = SMEM_X_OFF + XTILE_BYTES;   // 76160
static constexpr int SMEM_MBAR_OFF = SMEM_OUT_OFF + 256 * 4;     // 77184
static constexpr int SMEM_TOTAL    = SMEM_MBAR_OFF + 16;         // 77200 (x3 <= 233472)
static constexpr int GRID          = 456;                // 3 CTAs/SM * 152 SMs
static constexpr int NT            = 256;

__device__ __forceinline__ uint32_t smem_u32(const void* p) {
    return (uint32_t)__cvta_generic_to_shared(p);
}
__device__ __forceinline__ void mbar_init(uint32_t a, uint32_t count) {
    asm volatile("mbarrier.init.shared.b64 [%0], %1;" :: "r"(a), "r"(count) : "memory");
}
__device__ __forceinline__ void mbar_expect_tx(uint32_t a, uint32_t bytes) {
    asm volatile("mbarrier.arrive.expect_tx.shared.b64 _, [%0], %1;" :: "r"(a), "r"(bytes) : "memory");
}
__device__ __forceinline__ void tma_bulk_g2s(uint32_t dst, const void* src, uint32_t bytes, uint32_t mbar) {
    asm volatile("cp.async.bulk.shared::cta.global.mbarrier::complete_tx::bytes [%0], [%1], %2, [%3];"
                 :: "r"(dst), "l"(src), "r"(bytes), "r"(mbar) : "memory");
}
__device__ __forceinline__ void mbar_wait(uint32_t a, uint32_t parity) {
    uint32_t done;
    asm volatile(
        "{\n\t.reg .pred p;\n\t"
        "mbarrier.try_wait.parity.acquire.cta.shared::cta.b64 p, [%1], %2;\n\t"
        "selp.b32 %0, 1, 0, p;\n\t}"
        : "=r"(done) : "r"(a), "r"(parity) : "memory");
    while (!done) {
        asm volatile(
            "{\n\t.reg .pred p;\n\t"
            "mbarrier.try_wait.parity.acquire.cta.shared::cta.b64 p, [%1], %2, 0x989680;\n\t"
            "selp.b32 %0, 1, 0, p;\n\t}"
            : "=r"(done) : "r"(a), "r"(parity) : "memory");
    }
}

// f32x2 helpers
__device__ __forceinline__ unsigned long long f32x2_pack(float lo, float hi) {
    unsigned long long r;
    asm("mov.b64 %0, {%1, %2};" : "=l"(r) : "f"(lo), "f"(hi));
    return r;
}
__device__ __forceinline__ void ffma2(unsigned long long& acc, unsigned long long a, unsigned long long b) {
    asm("fma.rn.f32x2 %0, %1, %2, %0;" : "+l"(acc) : "l"(a), "l"(b));
}
__device__ __forceinline__ float f32x2_hsum(unsigned long long v) {
    float lo, hi;
    asm("mov.b64 {%0, %1}, %2;" : "=f"(lo), "=f"(hi) : "l"(v));
    return lo + hi;
}
// Direct b64 shared load: weight float2 lands as a packed f32x2 operand.
__device__ __forceinline__ unsigned long long lds_b64(uint32_t addr) {
    unsigned long long r;
    asm volatile("ld.shared.b64 %0, [%1];" : "=l"(r) : "r"(addr));
    return r;
}

__global__ void __launch_bounds__(NT, 3)
xonv2d_kernel(const float* __restrict__ x,
              const float* __restrict__ wts,
              const float* __restrict__ bias,
              float* __restrict__ out)
{
    extern __shared__ char smem[];
    float*   swt  = reinterpret_cast<float*>(smem);
    __half*  sxh  = reinterpret_cast<__half*>(smem + SMEM_X_OFF);
    const uint2* sxu2 = reinterpret_cast<const uint2*>(smem + SMEM_X_OFF);
    float*   sof  = reinterpret_cast<float*>(smem + SMEM_OUT_OFF);
    float4*  sof4 = reinterpret_cast<float4*>(smem + SMEM_OUT_OFF);
    const uint32_t mb = smem_u32(smem + SMEM_MBAR_OFF);
    const uint32_t swt_u32 = smem_u32(smem);

    const int t   = threadIdx.x;
    const int bid = blockIdx.x;

    if (t == 0) { mbar_init(mb, 1); mbar_init(mb + 8, 1); }
    __syncthreads();

    // Prologue: weight TMA for chunks bid (slot0), bid+GRID (slot1).
    if (t == 0) {
        mbar_expect_tx(mb, CHUNK_BYTES);
        tma_bulk_g2s(swt_u32, wts + (size_t)bid * CHUNK_FLOATS, CHUNK_BYTES, mb);
        mbar_expect_tx(mb + 8, CHUNK_BYTES);
        tma_bulk_g2s(swt_u32 + CHUNK_BYTES,
                     wts + (size_t)(bid + GRID) * CHUNK_FLOATS, CHUNK_BYTES, mb + 8);
    }

    // Lane mapping: o0l=bit0, ch=bits1-3 (cin pair), o0h=bit4; warp: o0m=bit5, px=bits6-7.
    const int o0  = (t & 1) + 2 * ((t >> 4) & 1) + 4 * ((t >> 5) & 1);
    const int ch  = (t >> 1) & 7;
    const int px  = (t >> 6) & 3;
    const uint32_t wbase = (uint32_t)(px * (FLOATS_PER_PX / 2) + o0 * 72 + ch * 9) * 8; // bytes
    const int xb = 2 * ch * CSTR + px;   // uint2 index; + cc*CSTR + r*6 + s (immediates)

    // Precomputed x-fill constants (loop-invariant). 1152 elements, 5 rounds of 256.
    int goff[5], sidx[5], pk[5];
    #pragma unroll
    for (int it = 0; it < 5; it++) {
        const int i = t + it * NT;
        if (i < XTILE_ELEMS) {
            const int wi = i % 6;
            const int r  = (i / 6) % 3;
            const int c  = (i / 18) % 16;
            const int b  = i / 288;
            goff[it] = ((b * 16 + c) * Hc + (r - 1)) * Wc + (wi - 1);
            sidx[it] = (c * CSTR + r * 6 + wi) * 4 + b;
            pk[it]   = r | (wi << 4);
        }
    }

    // x prefetch for first chunk.
    float xr[5];
    {
        const int p0 = bid * 4;
        const int h0 = p0 >> 7, w0 = p0 & 127;
        #pragma unroll
        for (int it = 0; it < 5; it++) {
            const int i = t + it * NT;
            if (i < XTILE_ELEMS) {
                const int hh = h0 + (pk[it] & 15) - 1;
                const int ww = w0 + (pk[it] >> 4) - 1;
                xr[it] = ((unsigned)hh < 128u && (unsigned)ww < 128u)
                         ? __ldg(x + goff[it] + p0) : 0.0f;
            }
        }
    }
    // bias prefetch for first chunk.
    float bs0 = 0.f, bs1 = 0.f, bs2 = 0.f, bs3 = 0.f;
    if (t < 64) {
        const float* bp = bias + (size_t)bid * 64 + (t & 15);
        bs0 = __ldg(bp); bs1 = __ldg(bp + 16); bs2 = __ldg(bp + 32); bs3 = __ldg(bp + 48);
    }

    for (int j = 0, gi = bid; gi < GROUPS; j++, gi += GRID) {
        const int slot   = j & 1;
        const int parity = (j >> 1) & 1;

        // STS x (fp16). Safe: S4(j-1) ordered all compute(j-1) x reads before this.
        #pragma unroll
        for (int it = 0; it < 5; it++) {
            const int i = t + it * NT;
            if (i < XTILE_ELEMS) sxh[sidx[it]] = __float2half_rn(xr[it]);
        }

        // Prefetch x + bias for next chunk (LDGs issued before the barrier).
        float bn0 = 0.f, bn1 = 0.f, bn2 = 0.f, bn3 = 0.f;
        {
            const int gn1 = gi + GRID;
            if (gn1 < GROUPS) {
                const int p1 = gn1 * 4;
                const int h0 = p1 >> 7, w0 = p1 & 127;
                #pragma unroll
                for (int it = 0; it < 5; it++) {
                    const int i = t + it * NT;
                    if (i < XTILE_ELEMS) {
                        const int hh = h0 + (pk[it] & 15) - 1;
                        const int ww = w0 + (pk[it] >> 4) - 1;
                        xr[it] = ((unsigned)hh < 128u && (unsigned)ww < 128u)
                                 ? __ldg(x + goff[it] + p1) : 0.0f;
                    }
                }
                if (t < 64) {
                    const float* bp = bias + (size_t)gn1 * 64 + (t & 15);
                    bn0 = __ldg(bp); bn1 = __ldg(bp + 16);
                    bn2 = __ldg(bp + 32); bn3 = __ldg(bp + 48);
                }
            }
        }

        __syncthreads();   // S2: x tile ready; prev STG sout reads done

        mbar_wait(mb + slot * 8, parity);  // weights for chunk gi ready

        const uint32_t wsh = swt_u32 + (uint32_t)slot * CHUNK_BYTES + wbase;
        const uint2*  xp = sxu2 + xb;

        // acc[cout][b] as f32x2 over (even tap, odd tap); result = .x + .y.
        unsigned long long ac00 = 0ull, ac01 = 0ull, ac02 = 0ull, ac03 = 0ull;
        unsigned long long ac10 = 0ull, ac11 = 0ull, ac12 = 0ull, ac13 = 0ull;

        #pragma unroll
        for (int k = 0; k < 9; k++) {
            // tap indices fA=2k, fB=2k+1 within the 18-float (cc,tap) sequence
            const int fA = 2 * k, fB = 2 * k + 1;
            const int offA = (fA / 9) * CSTR + ((fA % 9) / 3) * 6 + (fA % 9) % 3;
            const int offB = (fB / 9) * CSTR + ((fB % 9) / 3) * 6 + (fB % 9) % 3;

            union { uint2 u; __half2 h[2]; } rawA, rawB;
            rawA.u = xp[offA];
            rawB.u = xp[offB];
            const float2 loA = __half22float2(rawA.h[0]);
            const float2 hiA = __half22float2(rawA.h[1]);
            const float2 loB = __half22float2(rawB.h[0]);
            const float2 hiB = __half22float2(rawB.h[1]);
            const unsigned long long p0 = f32x2_pack(loA.x, loB.x);  // batch 0
            const unsigned long long p1 = f32x2_pack(loA.y, loB.y);  // batch 1
            const unsigned long long p2 = f32x2_pack(hiA.x, hiB.x);  // batch 2
            const unsigned long long p3 = f32x2_pack(hiA.y, hiB.y);  // batch 3

            const unsigned long long w0 = lds_b64(wsh + k * 8);          // cout o0  (w[2k],w[2k+1])
            const unsigned long long w1 = lds_b64(wsh + 4608 + k * 8);   // cout o0+8 (576 float2 = 4608B)

            ffma2(ac00, w0, p0);  ffma2(ac01, w0, p1);
            ffma2(ac02, w0, p2);  ffma2(ac03, w0, p3);
            ffma2(ac10, w1, p0);  ffma2(ac11, w1, p1);
            ffma2(ac12, w1, p2);  ffma2(ac13, w1, p3);
        }

        float a00 = f32x2_hsum(ac00), a01 = f32x2_hsum(ac01);
        float a02 = f32x2_hsum(ac02), a03 = f32x2_hsum(ac03);
        float a10 = f32x2_hsum(ac10), a11 = f32x2_hsum(ac11);
        float a12 = f32x2_hsum(ac12), a13 = f32x2_hsum(ac13);

        // Reduce over ch (lane bits 1-3): 3 butterflies.
        #pragma unroll
        for (int m = 2; m <= 8; m <<= 1) {
            a00 += __shfl_xor_sync(0xffffffffu, a00, m);
            a01 += __shfl_xor_sync(0xffffffffu, a01, m);
            a02 += __shfl_xor_sync(0xffffffffu, a02, m);
            a03 += __shfl_xor_sync(0xffffffffu, a03, m);
            a10 += __shfl_xor_sync(0xffffffffu, a10, m);
            a11 += __shfl_xor_sync(0xffffffffu, a11, m);
            a12 += __shfl_xor_sync(0xffffffffu, a12, m);
            a13 += __shfl_xor_sync(0xffffffffu, a13, m);
        }

        // Stage outputs into the dedicated sout buffer.
        if (ch == 0) {
            const int o1 = o0 + 8;
            sof[(0 * 16 + o0) * 4 + px] = a00;
            sof[(1 * 16 + o0) * 4 + px] = a01;
            sof[(2 * 16 + o0) * 4 + px] = a02;
            sof[(3 * 16 + o0) * 4 + px] = a03;
            sof[(0 * 16 + o1) * 4 + px] = a10;
            sof[(1 * 16 + o1) * 4 + px] = a11;
            sof[(2 * 16 + o1) * 4 + px] = a12;
            sof[(3 * 16 + o1) * 4 + px] = a13;
        }
        __syncthreads();   // S4: sout ready; all x-tile + weight-slot reads of chunk j done

        // Weight TMA for chunk j+2 into this (now free) slot.
        if (t == 0) {
            const int gn = gi + 2 * GRID;
            if (gn < GROUPS) {
                mbar_expect_tx(mb + slot * 8, CHUNK_BYTES);
                tma_bulk_g2s(swt_u32 + (uint32_t)slot * CHUNK_BYTES,
                             wts + (size_t)gn * CHUNK_FLOATS, CHUNK_BYTES, mb + slot * 8);
            }
        }

        // Coalesced write: thread t<64 -> (b = t>>4, o = t&15), float4 over 4 pixels.
        if (t < 64) {
            float4 v = sof4[t];
            v.x += bs0; v.y += bs1; v.z += bs2; v.w += bs3;
            *reinterpret_cast<float4*>(out + (size_t)t * (Hc * Wc) + gi * 4) = v;
            bs0 = bn0; bs1 = bn1; bs2 = bn2; bs3 = bn3;
        }
    }
}

extern "C" void kernel_launch(void* const* d_in, const int* in_sizes, int n_in,
                              void* d_out, int out_size) {
    const float* x    = (const float*)d_in[0];
    const float* wts  = (const float*)d_in[1];
    const float* bias = (const float*)d_in[2];
    float* out        = (float*)d_out;

    cudaFuncSetAttribute(xonv2d_kernel, cudaFuncAttributeMaxDynamicSharedMemorySize, SMEM_TOTAL);
    xonv2d_kernel<<<GRID, NT, SMEM_TOTAL>>>(x, wts, bias, out);
}